// round 13
// baseline (speedup 1.0000x reference)
#include <cuda_runtime.h>
#include <cuda_bf16.h>
#include <math.h>

#define F        128
#define TWO_F    256
#define KAGG     16
#define TILE     32          // rows per tile
#define NPROD    12          // producer warps
#define NCONS    4           // consumer warps
#define THREADS  512
#define NSLOT    3           // pipeline depth
#define B        256

// Scratch (static __device__ arrays: allowed; no runtime allocation)
__device__ float g_h2m[4096 * F];   // 16-row means of h2 (2 MB)
__device__ float g_h1m[256  * F];   // 16-row means of h1 (128 KB)
__device__ float g_h0 [256  * F];   // h0 (128 KB)

// ---- SMEM layout (bytes) --------------------------------------------------
#define SM_BIAS  0                        // 128 floats (512 B)
#define SM_MBAR  512                      // 6 mbarriers (full[3], empty[3])
#define SM_BHI   1024                     // Wt hi [128n][256k] bf16 (64 KB)
#define SM_BLO   (SM_BHI + 65536)         // Wt lo (64 KB)
#define SM_A     (SM_BLO + 65536)         // 3 slots x (hi 16 KB + lo 16 KB)
#define ABUF_SZ  (TILE * 512)             // 16384 B per half
#define SLOT_SZ  (2 * ABUF_SZ)            // 32768 B
#define SM_TOTAL (SM_A + NSLOT * SLOT_SZ) // 230400 B

__device__ __forceinline__ unsigned smem_u32(const void* p) {
    unsigned a;
    asm("{ .reg .u64 t; cvta.to.shared.u64 t, %1; cvt.u32.u64 %0, t; }"
        : "=r"(a) : "l"(p));
    return a;
}
__device__ __forceinline__ void mbar_init(unsigned a, unsigned cnt) {
    asm volatile("mbarrier.init.shared.b64 [%0], %1;" :: "r"(a), "r"(cnt) : "memory");
}
__device__ __forceinline__ void mbar_arrive(unsigned a) {
    asm volatile("mbarrier.arrive.shared.b64 _, [%0];" :: "r"(a) : "memory");
}
__device__ __forceinline__ void mbar_wait(unsigned a, unsigned ph) {
    asm volatile(
        "{\n\t.reg .pred P;\n\t"
        "WL_%=:\n\t"
        "mbarrier.try_wait.parity.acquire.cta.shared::cta.b64 P, [%0], %1, 0x989680;\n\t"
        "@P bra.uni WD_%=;\n\t"
        "bra.uni WL_%=;\n\t"
        "WD_%=:\n\t}"
        :: "r"(a), "r"(ph) : "memory");
}
__device__ __forceinline__ unsigned pack_bf16x2(float a, float b) {
    unsigned short x = __bfloat16_as_ushort(__float2bfloat16(a));
    unsigned short y = __bfloat16_as_ushort(__float2bfloat16(b));
    return (unsigned)x | ((unsigned)y << 16);
}
__device__ __forceinline__ void ldsm4(unsigned* r, unsigned addr) {
    asm volatile("ldmatrix.sync.aligned.m8n8.x4.shared.b16 {%0,%1,%2,%3}, [%4];"
                 : "=r"(r[0]), "=r"(r[1]), "=r"(r[2]), "=r"(r[3]) : "r"(addr));
}
__device__ __forceinline__ void mma16816(float* c, const unsigned* a,
                                         unsigned b0, unsigned b1) {
    asm volatile(
        "mma.sync.aligned.m16n8k16.row.col.f32.bf16.bf16.f32 "
        "{%0,%1,%2,%3}, {%4,%5,%6,%7}, {%8,%9}, {%0,%1,%2,%3};"
        : "+f"(c[0]), "+f"(c[1]), "+f"(c[2]), "+f"(c[3])
        : "r"(a[0]), "r"(a[1]), "r"(a[2]), "r"(a[3]), "r"(b0), "r"(b1));
}

// store one row's concat half (bf16 hi/lo split) into swizzled A slot
__device__ __forceinline__ void store_half(char* sm, unsigned pb, unsigned rbase,
                                           unsigned rx, unsigned l2, unsigned sub8,
                                           unsigned kchunk_base,
                                           float a0, float a1, float a2, float a3) {
    const unsigned off = rbase + (((kchunk_base + l2) ^ rx) << 4) + sub8;
    float h0 = __bfloat162float(__float2bfloat16(a0));
    float h1 = __bfloat162float(__float2bfloat16(a1));
    float h2 = __bfloat162float(__float2bfloat16(a2));
    float h3 = __bfloat162float(__float2bfloat16(a3));
    *(uint2*)(sm + pb + off) =
        make_uint2(pack_bf16x2(a0, a1), pack_bf16x2(a2, a3));
    *(uint2*)(sm + pb + ABUF_SZ + off) =
        make_uint2(pack_bf16x2(a0 - h0, a1 - h1), pack_bf16x2(a2 - h2, a3 - h3));
}

// ---------------------------------------------------------------------------
// Warp-specialized tensor-core SAGE layer with mbarrier ring pipeline.
// AGG_IN=1 : concat(mean_16 nbr[r*16..], self[r]);  AGG_IN=0: concat(nbr[r], self[r])
// MEAN_OUT=1: write only 16-row group means of relu output.
// Producers (warps 0-11) free-run up to NSLOT tiles ahead -> DRAM never idles
// on consumer work. Consumers (warps 12-15) HMMA bf16 3-product GEMM.
// ---------------------------------------------------------------------------
template<int AGG_IN, int MEAN_OUT>
__global__ void __launch_bounds__(THREADS, 1)
sage_mma(const float* __restrict__ nbr,
         const float* __restrict__ selfx,
         const float* __restrict__ W,
         const float* __restrict__ bias,
         float* __restrict__ out,
         int ntiles)
{
    extern __shared__ char sm[];
    const int tid = threadIdx.x;
    const int wid = tid >> 5;
    const int lid = tid & 31;
    const unsigned smb = smem_u32(sm);

    int n = 0;
    for (int t = blockIdx.x; t < ntiles; t += gridDim.x) n++;
    if (n == 0) return;

    // ---- stage W^T hi/lo (swizzled, STS.128 conflict-free) + bias ----
    for (int c = tid; c < 32 * F; c += THREADS) {
        const int nn = c >> 5, ch = c & 31;
        float w[8], wh[8];
        #pragma unroll
        for (int i = 0; i < 8; ++i) {
            w[i]  = W[(ch * 8 + i) * F + nn];
            wh[i] = __bfloat162float(__float2bfloat16(w[i]));
        }
        uint4 hi, lo;
        hi.x = pack_bf16x2(w[0], w[1]); hi.y = pack_bf16x2(w[2], w[3]);
        hi.z = pack_bf16x2(w[4], w[5]); hi.w = pack_bf16x2(w[6], w[7]);
        lo.x = pack_bf16x2(w[0]-wh[0], w[1]-wh[1]);
        lo.y = pack_bf16x2(w[2]-wh[2], w[3]-wh[3]);
        lo.z = pack_bf16x2(w[4]-wh[4], w[5]-wh[5]);
        lo.w = pack_bf16x2(w[6]-wh[6], w[7]-wh[7]);
        const unsigned off = (unsigned)nn * 512
                           + (((unsigned)(ch ^ (nn & 7))) << 4);
        *(uint4*)(sm + SM_BHI + off) = hi;
        *(uint4*)(sm + SM_BLO + off) = lo;
    }
    if (tid < F) ((float*)(sm + SM_BIAS))[tid] = bias[tid];
    if (tid == 0) {
        #pragma unroll
        for (int s = 0; s < NSLOT; ++s) {
            mbar_init(smb + SM_MBAR + s * 16,     NPROD * 32);   // full[s]
            mbar_init(smb + SM_MBAR + s * 16 + 8, NCONS * 32);   // empty[s]
        }
    }
    __syncthreads();

    const float* bias_s = (const float*)(sm + SM_BIAS);

    // ldmatrix lane geometry
    const unsigned row_off = (lid & 7) + ((lid >> 3) & 1) * 8;
    const unsigned chalf   = (unsigned)(lid >> 4);

    if (wid < NPROD) {
        // ================= producer =================
        const unsigned l2 = (unsigned)(lid >> 1);
        const unsigned sub8 = (unsigned)(lid & 1) * 8;
        int slot = 0, phase = 1;                       // first empty-wait passes
        for (int i = 0; i < n; ++i) {
            const unsigned fullb  = smb + SM_MBAR + slot * 16;
            const unsigned emptyb = fullb + 8;
            mbar_wait(emptyb, phase);
            const unsigned pb = SM_A + slot * SLOT_SZ;

            const int  tile = blockIdx.x + i * gridDim.x;
            const long tg0  = (long)tile * TILE;
            for (int row = wid; row < TILE; row += NPROD) {
                const long rg = tg0 + row;
                const unsigned rbase = (unsigned)row * 512;
                const unsigned rx = (unsigned)row & 7;

                float a0, a1, a2, a3;
                if (AGG_IN) {
                    const float4* nb = (const float4*)(nbr + rg * (KAGG * F)) + lid;
                    float4 v[KAGG];
                    #pragma unroll
                    for (int k = 0; k < KAGG; ++k) v[k] = nb[k * (F / 4)];
                    #pragma unroll
                    for (int s = KAGG / 2; s > 0; s >>= 1)
                        #pragma unroll
                        for (int k = 0; k < s; ++k) {
                            v[k].x += v[k + s].x; v[k].y += v[k + s].y;
                            v[k].z += v[k + s].z; v[k].w += v[k + s].w;
                        }
                    const float sc = 1.0f / 16.0f;
                    a0 = v[0].x * sc; a1 = v[0].y * sc;
                    a2 = v[0].z * sc; a3 = v[0].w * sc;
                } else {
                    float4 p = ((const float4*)(nbr + rg * F))[lid];
                    a0 = p.x; a1 = p.y; a2 = p.z; a3 = p.w;
                }
                store_half(sm, pb, rbase, rx, l2, sub8, 0u, a0, a1, a2, a3);
                float4 sv = ((const float4*)(selfx + rg * F))[lid];
                store_half(sm, pb, rbase, rx, l2, sub8, 16u, sv.x, sv.y, sv.z, sv.w);
            }
            mbar_arrive(fullb);
            if (++slot == NSLOT) { slot = 0; phase ^= 1; }
        }
    } else {
        // ================= consumer =================
        const int cw = wid - NPROD;                    // 0..3
        const unsigned m0 = (unsigned)(cw >> 1) * 16;
        const unsigned n0 = (unsigned)(cw & 1) * 64;
        const unsigned rA  = m0 + row_off;
        const unsigned rAb = rA * 512, rAx = rA & 7;
        unsigned rBb[4], rBx[4];
        #pragma unroll
        for (int j = 0; j < 4; ++j) {
            const unsigned rB = n0 + j * 16 + row_off;
            rBb[j] = rB * 512; rBx[j] = rB & 7;
        }

        int slot = 0, phase = 0;
        for (int i = 0; i < n; ++i) {
            const unsigned fullb  = smb + SM_MBAR + slot * 16;
            const unsigned emptyb = fullb + 8;
            mbar_wait(fullb, phase);
            const unsigned cb = SM_A + slot * SLOT_SZ;

            const int  tile = blockIdx.x + i * gridDim.x;
            const long tg0  = (long)tile * TILE;

            float c[8][4];
            #pragma unroll
            for (int j = 0; j < 8; ++j)
                #pragma unroll
                for (int q = 0; q < 4; ++q) c[j][q] = 0.f;

            #pragma unroll
            for (int s = 0; s < 16; ++s) {
                const unsigned ch = (unsigned)(s * 2) + chalf;
                unsigned ahi[4], alo[4];
                ldsm4(ahi, smb + cb + rAb + ((ch ^ rAx) << 4));
                ldsm4(alo, smb + cb + ABUF_SZ + rAb + ((ch ^ rAx) << 4));
                #pragma unroll
                for (int j = 0; j < 4; ++j) {
                    unsigned bh[4], bl[4];
                    ldsm4(bh, smb + SM_BHI + rBb[j] + ((ch ^ rBx[j]) << 4));
                    ldsm4(bl, smb + SM_BLO + rBb[j] + ((ch ^ rBx[j]) << 4));
                    mma16816(c[2*j],   ahi, bh[0], bh[2]);
                    mma16816(c[2*j+1], ahi, bh[1], bh[3]);
                    mma16816(c[2*j],   ahi, bl[0], bl[2]);
                    mma16816(c[2*j+1], ahi, bl[1], bl[3]);
                    mma16816(c[2*j],   alo, bh[0], bh[2]);
                    mma16816(c[2*j+1], alo, bh[1], bh[3]);
                }
            }
            mbar_arrive(emptyb);                       // A consumed; free the slot

            // ---- epilogue (off the critical pipeline path) ----
            const int g = lid >> 2, tt = lid & 3;
            if (MEAN_OUT) {
                float sj[8][2];
                #pragma unroll
                for (int j = 0; j < 8; ++j) {
                    const int col = n0 + j * 8 + tt * 2;
                    const float b0 = bias_s[col], b1 = bias_s[col + 1];
                    sj[j][0] = fmaxf(c[j][0] + b0, 0.f) + fmaxf(c[j][2] + b0, 0.f);
                    sj[j][1] = fmaxf(c[j][1] + b1, 0.f) + fmaxf(c[j][3] + b1, 0.f);
                }
                #pragma unroll
                for (int off = 4; off <= 16; off <<= 1)
                    #pragma unroll
                    for (int j = 0; j < 8; ++j) {
                        sj[j][0] += __shfl_xor_sync(0xffffffffu, sj[j][0], off);
                        sj[j][1] += __shfl_xor_sync(0xffffffffu, sj[j][1], off);
                    }
                if (lid < 4) {
                    const long grow = (long)tile * 2 + (m0 >> 4);
                    #pragma unroll
                    for (int j = 0; j < 8; ++j)
                        *(float2*)(out + grow * F + n0 + j * 8 + lid * 2) =
                            make_float2(sj[j][0] * (1.0f / 16.0f),
                                        sj[j][1] * (1.0f / 16.0f));
                }
            } else {
                const long row1 = tg0 + m0 + g;
                const long row2 = row1 + 8;
                #pragma unroll
                for (int j = 0; j < 8; ++j) {
                    const int col = n0 + j * 8 + tt * 2;
                    const float b0 = bias_s[col], b1 = bias_s[col + 1];
                    float2 o1 = make_float2(fmaxf(c[j][0] + b0, 0.f),
                                            fmaxf(c[j][1] + b1, 0.f));
                    float2 o2 = make_float2(fmaxf(c[j][2] + b0, 0.f),
                                            fmaxf(c[j][3] + b1, 0.f));
                    *(float2*)(out + row1 * F + col) = o1;
                    *(float2*)(out + row2 * F + col) = o2;
                }
            }
            if (++slot == NSLOT) { slot = 0; phase ^= 1; }
        }
    }
}

// ---------------------------------------------------------------------------
// Head: z = h0 @ lin1_W + lin1_b ; BatchNorm (batch stats) ; sigmoid(lin2).
// ---------------------------------------------------------------------------
#define HS_H0   0
#define HS_W    (B * F)
#define HS_SUM  (HS_W + F * 8)
#define HS_SQ   (HS_SUM + 64)
#define HS_TOTAL ((HS_SQ + 64) * 4)

__global__ void __launch_bounds__(256, 1)
head_kernel(const float* __restrict__ h0,
            const float* __restrict__ l1W,
            const float* __restrict__ l1b,
            const float* __restrict__ gamma,
            const float* __restrict__ beta,
            const float* __restrict__ l2W,
            const float* __restrict__ l2b,
            float* __restrict__ out)
{
    extern __shared__ float hsm[];
    float* sh0  = hsm + HS_H0;
    float* sW   = hsm + HS_W;
    float* wsum = hsm + HS_SUM;
    float* wsq  = hsm + HS_SQ;

    const int i   = threadIdx.x;
    const int wid = i >> 5;
    const int lid = i & 31;

    {
        const float4* g4 = (const float4*)h0;
        float4* s4 = (float4*)sh0;
        #pragma unroll
        for (int it = 0; it < (B * F / 4) / 256; ++it) {
            const int idx = i + it * 256;
            const int row = idx >> 5, q = idx & 31;
            s4[row * 32 + (q ^ (row & 31))] = g4[idx];
        }
    }
    for (int t = i; t < F * 8; t += 256) sW[t] = l1W[t];
    __syncthreads();

    float z[8];
    #pragma unroll
    for (int j = 0; j < 8; ++j) z[j] = l1b[j];

    const float4* hr = (const float4*)sh0 + (size_t)i * 32;
    #pragma unroll
    for (int f4 = 0; f4 < F / 4; ++f4) {
        float4 h = hr[f4 ^ (i & 31)];
        #pragma unroll
        for (int j = 0; j < 8; ++j)
            z[j] += h.x * sW[(4 * f4 + 0) * 8 + j]
                  + h.y * sW[(4 * f4 + 1) * 8 + j]
                  + h.z * sW[(4 * f4 + 2) * 8 + j]
                  + h.w * sW[(4 * f4 + 3) * 8 + j];
    }

    float rs_[8], rq_[8];
    #pragma unroll
    for (int j = 0; j < 8; ++j) { rs_[j] = z[j]; rq_[j] = z[j] * z[j]; }
    #pragma unroll
    for (int off = 16; off > 0; off >>= 1) {
        #pragma unroll
        for (int j = 0; j < 8; ++j) {
            rs_[j] += __shfl_xor_sync(0xffffffffu, rs_[j], off);
            rq_[j] += __shfl_xor_sync(0xffffffffu, rq_[j], off);
        }
    }
    if (lid == 0) {
        #pragma unroll
        for (int j = 0; j < 8; ++j) {
            wsum[wid * 8 + j] = rs_[j];
            wsq [wid * 8 + j] = rq_[j];
        }
    }
    __syncthreads();

    float zn[8];
    #pragma unroll
    for (int j = 0; j < 8; ++j) {
        float su = 0.f, sq = 0.f;
        #pragma unroll
        for (int w = 0; w < 8; ++w) { su += wsum[w * 8 + j]; sq += wsq[w * 8 + j]; }
        float mu  = su * (1.0f / 256.0f);
        float var = sq * (1.0f / 256.0f) - mu * mu;
        float rs  = rsqrtf(var + 1e-5f);
        zn[j] = (z[j] - mu) * rs * gamma[j] + beta[j];
    }

    #pragma unroll
    for (int c = 0; c < 2; ++c) {
        float o = l2b[c];
        #pragma unroll
        for (int j = 0; j < 8; ++j) o += zn[j] * l2W[j * 2 + c];
        out[i * 2 + c] = 1.0f / (1.0f + expf(-o));
    }
}

// ---------------------------------------------------------------------------
extern "C" void kernel_launch(void* const* d_in, const int* in_sizes, int n_in,
                              void* d_out, int out_size)
{
    const float* x0    = (const float*)d_in[0];
    const float* x1    = (const float*)d_in[1];
    const float* x2    = (const float*)d_in[2];
    const float* x3    = (const float*)d_in[3];
    const float* W0    = (const float*)d_in[4];
    const float* b0    = (const float*)d_in[5];
    const float* W1    = (const float*)d_in[6];
    const float* b1    = (const float*)d_in[7];
    const float* W2    = (const float*)d_in[8];
    const float* b2    = (const float*)d_in[9];
    const float* l1W   = (const float*)d_in[10];
    const float* l1b   = (const float*)d_in[11];
    const float* gamma = (const float*)d_in[12];
    const float* beta  = (const float*)d_in[13];
    const float* l2W   = (const float*)d_in[14];
    const float* l2b   = (const float*)d_in[15];
    float* out = (float*)d_out;

    void *p2 = nullptr, *p1 = nullptr, *p0 = nullptr;
    cudaGetSymbolAddress(&p2, g_h2m);
    cudaGetSymbolAddress(&p1, g_h1m);
    cudaGetSymbolAddress(&p0, g_h0);
    float* h2m = (float*)p2;
    float* h1m = (float*)p1;
    float* h0  = (float*)p0;

    cudaFuncSetAttribute(sage_mma<1, 1>,
                         cudaFuncAttributeMaxDynamicSharedMemorySize, SM_TOTAL);
    cudaFuncSetAttribute(sage_mma<0, 1>,
                         cudaFuncAttributeMaxDynamicSharedMemorySize, SM_TOTAL);
    cudaFuncSetAttribute(sage_mma<0, 0>,
                         cudaFuncAttributeMaxDynamicSharedMemorySize, SM_TOTAL);
    cudaFuncSetAttribute(head_kernel,
                         cudaFuncAttributeMaxDynamicSharedMemorySize, HS_TOTAL);

    // K3: agg(x3) ++ x2 -> relu GEMM -> 16-row means (h2m: 4096 x 128)
    sage_mma<1, 1><<<148, THREADS, SM_TOTAL>>>(x3, x2, W2, b2, h2m, 2048);
    // K2: h2m ++ x1 -> relu GEMM -> 16-row means (h1m: 256 x 128)
    sage_mma<0, 1><<<128, THREADS, SM_TOTAL>>>(h2m, x1, W1, b1, h1m, 128);
    // K1: h1m ++ x0 -> relu GEMM -> full h0 (256 x 128)
    sage_mma<0, 0><<<8, THREADS, SM_TOTAL>>>(h1m, x0, W0, b0, h0, 8);
    // Head
    head_kernel<<<1, 256, HS_TOTAL>>>(h0, l1W, l1b, gamma, beta, l2W, l2b, out);
}

// round 17
// speedup vs baseline: 1.1140x; 1.1140x over previous
#include <cuda_runtime.h>
#include <cuda_bf16.h>
#include <math.h>

#define F        128
#define TWO_F    256
#define KAGG     16
#define TILE     32          // rows per tile
#define NPROD    12          // producer warps
#define THREADS  512
#define B        256

// Scratch (static __device__ arrays: allowed; no runtime allocation)
__device__ float g_h2m[4096 * F];   // 16-row means of h2 (2 MB)
__device__ float g_h1m[256  * F];   // 16-row means of h1 (128 KB)
__device__ float g_h0 [256  * F];   // h0 (128 KB)

// ---- SMEM layout (bytes) --------------------------------------------------
// swizzled bf16 tiles, row stride 512 B (256 k-elems):
//   byte(row,k) = row*512 + (((k>>3) ^ (row&7)) << 4) + (k&7)*2
#define SM_BIAS  0                        // 128 floats
#define SM_BHI   1024                     // Wt hi [128n][256k] bf16 (64 KB)
#define SM_BLO   (SM_BHI + 65536)         // Wt lo (64 KB)
#define SM_A     (SM_BLO + 65536)         // 2 buffers x (hi 16 KB + lo 16 KB)
#define ABUF_SZ  (TILE * 512)             // 16384 B per half
#define SM_TOTAL (SM_A + 4 * ABUF_SZ)     // 197632 B

__device__ __forceinline__ unsigned smem_u32(const void* p) {
    unsigned a;
    asm("{ .reg .u64 t; cvta.to.shared.u64 t, %1; cvt.u32.u64 %0, t; }"
        : "=r"(a) : "l"(p));
    return a;
}
__device__ __forceinline__ unsigned pack_bf16x2(float a, float b) {
    unsigned short x = __bfloat16_as_ushort(__float2bfloat16(a));
    unsigned short y = __bfloat16_as_ushort(__float2bfloat16(b));
    return (unsigned)x | ((unsigned)y << 16);
}
__device__ __forceinline__ void ldsm4(unsigned* r, unsigned addr) {
    asm volatile("ldmatrix.sync.aligned.m8n8.x4.shared.b16 {%0,%1,%2,%3}, [%4];"
                 : "=r"(r[0]), "=r"(r[1]), "=r"(r[2]), "=r"(r[3]) : "r"(addr));
}
__device__ __forceinline__ void mma16816(float* c, const unsigned* a,
                                         unsigned b0, unsigned b1) {
    asm volatile(
        "mma.sync.aligned.m16n8k16.row.col.f32.bf16.bf16.f32 "
        "{%0,%1,%2,%3}, {%4,%5,%6,%7}, {%8,%9}, {%0,%1,%2,%3};"
        : "+f"(c[0]), "+f"(c[1]), "+f"(c[2]), "+f"(c[3])
        : "r"(a[0]), "r"(a[1]), "r"(a[2]), "r"(a[3]), "r"(b0), "r"(b1));
}

// store one row's concat half (bf16 hi/lo split) into swizzled A buffer
__device__ __forceinline__ void store_half(char* sm, unsigned pb, unsigned rbase,
                                           unsigned rx, unsigned l2, unsigned sub8,
                                           unsigned kchunk_base,
                                           float a0, float a1, float a2, float a3) {
    const unsigned off = rbase + (((kchunk_base + l2) ^ rx) << 4) + sub8;
    float h0 = __bfloat162float(__float2bfloat16(a0));
    float h1 = __bfloat162float(__float2bfloat16(a1));
    float h2 = __bfloat162float(__float2bfloat16(a2));
    float h3 = __bfloat162float(__float2bfloat16(a3));
    *(uint2*)(sm + pb + off) =
        make_uint2(pack_bf16x2(a0, a1), pack_bf16x2(a2, a3));
    *(uint2*)(sm + pb + ABUF_SZ + off) =
        make_uint2(pack_bf16x2(a0 - h0, a1 - h1), pack_bf16x2(a2 - h2, a3 - h3));
}

// ---------------------------------------------------------------------------
// Warp-specialized tensor-core SAGE layer (R11 structure: __syncthreads-locked
// double buffer — measured best). AGG_IN / MEAN_OUT as before. tile0 shifts
// the global tile id (K3 is split into two launches for ncu alignment).
// ---------------------------------------------------------------------------
template<int AGG_IN, int MEAN_OUT>
__global__ void __launch_bounds__(THREADS, 1)
sage_mma(const float* __restrict__ nbr,
         const float* __restrict__ selfx,
         const float* __restrict__ W,
         const float* __restrict__ bias,
         float* __restrict__ out,
         int ntiles, int tile0)
{
    extern __shared__ char sm[];
    const int tid = threadIdx.x;
    const int wid = tid >> 5;
    const int lid = tid & 31;
    const unsigned smb = smem_u32(sm);

    int n = 0;
    for (int t = blockIdx.x; t < ntiles; t += gridDim.x) n++;
    if (n == 0) return;

    // ---- stage W^T hi/lo (swizzled, STS.128 conflict-free) + bias ----
    for (int c = tid; c < 32 * F; c += THREADS) {
        const int nn = c >> 5, ch = c & 31;
        float w[8], wh[8];
        #pragma unroll
        for (int i = 0; i < 8; ++i) {
            w[i]  = __ldg(&W[(ch * 8 + i) * F + nn]);
            wh[i] = __bfloat162float(__float2bfloat16(w[i]));
        }
        uint4 hi, lo;
        hi.x = pack_bf16x2(w[0], w[1]); hi.y = pack_bf16x2(w[2], w[3]);
        hi.z = pack_bf16x2(w[4], w[5]); hi.w = pack_bf16x2(w[6], w[7]);
        lo.x = pack_bf16x2(w[0]-wh[0], w[1]-wh[1]);
        lo.y = pack_bf16x2(w[2]-wh[2], w[3]-wh[3]);
        lo.z = pack_bf16x2(w[4]-wh[4], w[5]-wh[5]);
        lo.w = pack_bf16x2(w[6]-wh[6], w[7]-wh[7]);
        const unsigned off = (unsigned)nn * 512
                           + (((unsigned)(ch ^ (nn & 7))) << 4);
        *(uint4*)(sm + SM_BHI + off) = hi;
        *(uint4*)(sm + SM_BLO + off) = lo;
    }
    if (tid < F) ((float*)(sm + SM_BIAS))[tid] = bias[tid];
    __syncthreads();

    const float* bias_s = (const float*)(sm + SM_BIAS);
    const bool producer = (wid < NPROD);

    // ldmatrix lane geometry
    const unsigned row_off = (lid & 7) + ((lid >> 3) & 1) * 8;
    const unsigned chalf   = (unsigned)(lid >> 4);

    for (int i = 0; i <= n; ++i) {
        const unsigned pb = (i & 1) ? (SM_A + 2 * ABUF_SZ) : SM_A;     // fill
        const unsigned cb = (i & 1) ? SM_A : (SM_A + 2 * ABUF_SZ);     // drain

        if (producer) {
            if (i < n) {
                const int  tile = tile0 + blockIdx.x + i * gridDim.x;
                const long tg0  = (long)(tile - tile0) * TILE;  // local row base
                const unsigned l2 = (unsigned)(lid >> 1);
                const unsigned sub8 = (unsigned)(lid & 1) * 8;

                for (int row = wid; row < TILE; row += NPROD) {
                    const long rg = tg0 + row;
                    const unsigned rbase = (unsigned)row * 512;
                    const unsigned rx = (unsigned)row & 7;

                    float a0, a1, a2, a3;
                    if (AGG_IN) {
                        const float4* nb = (const float4*)(nbr + rg * (KAGG * F)) + lid;
                        float4 v[KAGG];
                        #pragma unroll
                        for (int k = 0; k < KAGG; ++k) v[k] = __ldg(&nb[k * (F / 4)]);
                        #pragma unroll
                        for (int s = KAGG / 2; s > 0; s >>= 1)
                            #pragma unroll
                            for (int k = 0; k < s; ++k) {
                                v[k].x += v[k + s].x; v[k].y += v[k + s].y;
                                v[k].z += v[k + s].z; v[k].w += v[k + s].w;
                            }
                        const float sc = 1.0f / 16.0f;
                        a0 = v[0].x * sc; a1 = v[0].y * sc;
                        a2 = v[0].z * sc; a3 = v[0].w * sc;
                    } else {
                        float4 p = __ldg(&((const float4*)(nbr + rg * F))[lid]);
                        a0 = p.x; a1 = p.y; a2 = p.z; a3 = p.w;
                    }
                    store_half(sm, pb, rbase, rx, l2, sub8, 0u, a0, a1, a2, a3);
                    float4 sv = __ldg(&((const float4*)(selfx + rg * F))[lid]);
                    store_half(sm, pb, rbase, rx, l2, sub8, 16u, sv.x, sv.y, sv.z, sv.w);
                }
            }
        } else if (i >= 1) {
            const int  tile = tile0 + blockIdx.x + (i - 1) * gridDim.x;
            const long tg0  = (long)(tile - tile0) * TILE;
            const int  cw   = wid - NPROD;            // 0..3
            const unsigned m0 = (unsigned)(cw >> 1) * 16;
            const unsigned n0 = (unsigned)(cw & 1) * 64;

            float c[8][4];
            #pragma unroll
            for (int j = 0; j < 8; ++j)
                #pragma unroll
                for (int q = 0; q < 4; ++q) c[j][q] = 0.f;

            const unsigned rA  = m0 + row_off;
            const unsigned rAb = rA * 512, rAx = rA & 7;
            unsigned rBb[4], rBx[4];
            #pragma unroll
            for (int j = 0; j < 4; ++j) {
                const unsigned rB = n0 + j * 16 + row_off;
                rBb[j] = rB * 512; rBx[j] = rB & 7;
            }

            #pragma unroll
            for (int s = 0; s < 16; ++s) {
                const unsigned ch = (unsigned)(s * 2) + chalf;
                unsigned ahi[4], alo[4];
                ldsm4(ahi, smb + cb + rAb + ((ch ^ rAx) << 4));
                ldsm4(alo, smb + cb + ABUF_SZ + rAb + ((ch ^ rAx) << 4));
                #pragma unroll
                for (int j = 0; j < 4; ++j) {
                    unsigned bh[4], bl[4];
                    ldsm4(bh, smb + SM_BHI + rBb[j] + ((ch ^ rBx[j]) << 4));
                    ldsm4(bl, smb + SM_BLO + rBb[j] + ((ch ^ rBx[j]) << 4));
                    mma16816(c[2*j],   ahi, bh[0], bh[2]);
                    mma16816(c[2*j+1], ahi, bh[1], bh[3]);
                    mma16816(c[2*j],   ahi, bl[0], bl[2]);
                    mma16816(c[2*j+1], ahi, bl[1], bl[3]);
                    mma16816(c[2*j],   alo, bh[0], bh[2]);
                    mma16816(c[2*j+1], alo, bh[1], bh[3]);
                }
            }

            // ---- epilogue ----
            const int g = lid >> 2, tt = lid & 3;
            if (MEAN_OUT) {
                float sj[8][2];
                #pragma unroll
                for (int j = 0; j < 8; ++j) {
                    const int col = n0 + j * 8 + tt * 2;
                    const float b0 = bias_s[col], b1 = bias_s[col + 1];
                    sj[j][0] = fmaxf(c[j][0] + b0, 0.f) + fmaxf(c[j][2] + b0, 0.f);
                    sj[j][1] = fmaxf(c[j][1] + b1, 0.f) + fmaxf(c[j][3] + b1, 0.f);
                }
                #pragma unroll
                for (int off = 4; off <= 16; off <<= 1)
                    #pragma unroll
                    for (int j = 0; j < 8; ++j) {
                        sj[j][0] += __shfl_xor_sync(0xffffffffu, sj[j][0], off);
                        sj[j][1] += __shfl_xor_sync(0xffffffffu, sj[j][1], off);
                    }
                if (lid < 4) {
                    const long grow = (long)tile * 2 + (m0 >> 4);
                    #pragma unroll
                    for (int j = 0; j < 8; ++j)
                        *(float2*)(out + grow * F + n0 + j * 8 + lid * 2) =
                            make_float2(sj[j][0] * (1.0f / 16.0f),
                                        sj[j][1] * (1.0f / 16.0f));
                }
            } else {
                const long row1 = (long)tile * TILE + m0 + g;
                const long row2 = row1 + 8;
                #pragma unroll
                for (int j = 0; j < 8; ++j) {
                    const int col = n0 + j * 8 + tt * 2;
                    const float b0 = bias_s[col], b1 = bias_s[col + 1];
                    float2 o1 = make_float2(fmaxf(c[j][0] + b0, 0.f),
                                            fmaxf(c[j][1] + b1, 0.f));
                    float2 o2 = make_float2(fmaxf(c[j][2] + b0, 0.f),
                                            fmaxf(c[j][3] + b1, 0.f));
                    *(float2*)(out + row1 * F + col) = o1;
                    *(float2*)(out + row2 * F + col) = o2;
                }
            }
        }
        __syncthreads();
    }
}

// ---------------------------------------------------------------------------
// Head: z = h0 @ lin1_W + lin1_b ; BatchNorm (batch stats) ; sigmoid(lin2).
// 512 threads = 2 per row (k-split 64/64, shfl combine). After the combine,
// the xor-{16,8,4,2} reduce sums each of the warp's 16 DISTINCT rows once,
// so warp totals cover 256 rows exactly once -> normalize by 256.
// ---------------------------------------------------------------------------
__global__ void __launch_bounds__(512, 1)
head_kernel(const float* __restrict__ h0,
            const float* __restrict__ l1W,   // [F, 8]
            const float* __restrict__ l1b,   // [8]
            const float* __restrict__ gamma, // [8]
            const float* __restrict__ beta,  // [8]
            const float* __restrict__ l2W,   // [8, 2]
            const float* __restrict__ l2b,   // [2]
            float* __restrict__ out)         // [B, 2]
{
    __shared__ float sW[F * 8];
    __shared__ float wsum[16][8];
    __shared__ float wsq [16][8];

    const int t    = threadIdx.x;
    const int wid  = t >> 5;
    const int lid  = t & 31;
    const int row  = t >> 1;
    const int half = t & 1;

    for (int i = t; i < F * 8; i += 512) sW[i] = l1W[i];
    __syncthreads();

    // partial z over this half's 64 k-values
    float z[8];
    #pragma unroll
    for (int j = 0; j < 8; ++j) z[j] = 0.f;
    const float4* hr = (const float4*)(h0 + (size_t)row * F) + half * 16;
    const float*  wk = sW + half * 64 * 8;
    #pragma unroll
    for (int f4 = 0; f4 < 16; ++f4) {
        float4 h = __ldg(&hr[f4]);
        #pragma unroll
        for (int j = 0; j < 8; ++j)
            z[j] += h.x * wk[(4 * f4 + 0) * 8 + j]
                  + h.y * wk[(4 * f4 + 1) * 8 + j]
                  + h.z * wk[(4 * f4 + 2) * 8 + j]
                  + h.w * wk[(4 * f4 + 3) * 8 + j];
    }
    // combine halves (both lanes of a pair end with the full-row z)
    #pragma unroll
    for (int j = 0; j < 8; ++j)
        z[j] += __shfl_xor_sync(0xffffffffu, z[j], 1);
    #pragma unroll
    for (int j = 0; j < 8; ++j) z[j] += l1b[j];

    // stats: xor-{16,8,4,2} sums the 16 distinct rows per bit0-class once
    float rs_[8], rq_[8];
    #pragma unroll
    for (int j = 0; j < 8; ++j) { rs_[j] = z[j]; rq_[j] = z[j] * z[j]; }
    #pragma unroll
    for (int off = 16; off > 1; off >>= 1) {
        #pragma unroll
        for (int j = 0; j < 8; ++j) {
            rs_[j] += __shfl_xor_sync(0xffffffffu, rs_[j], off);
            rq_[j] += __shfl_xor_sync(0xffffffffu, rq_[j], off);
        }
    }
    if (lid == 0) {
        #pragma unroll
        for (int j = 0; j < 8; ++j) { wsum[wid][j] = rs_[j]; wsq[wid][j] = rq_[j]; }
    }
    __syncthreads();

    float zn[8];
    #pragma unroll
    for (int j = 0; j < 8; ++j) {
        float su = 0.f, sq = 0.f;
        #pragma unroll
        for (int w = 0; w < 16; ++w) { su += wsum[w][j]; sq += wsq[w][j]; }
        float mu  = su * (1.0f / 256.0f);               // 256 rows, each once
        float var = sq * (1.0f / 256.0f) - mu * mu;
        float rs  = rsqrtf(var + 1e-5f);
        zn[j] = (z[j] - mu) * rs * gamma[j] + beta[j];
    }

    // thread (row, half) writes class c = half
    {
        const int c = half;
        float o = l2b[c];
        #pragma unroll
        for (int j = 0; j < 8; ++j) o += zn[j] * l2W[j * 2 + c];
        out[row * 2 + c] = 1.0f / (1.0f + expf(-o));
    }
}

// ---------------------------------------------------------------------------
extern "C" void kernel_launch(void* const* d_in, const int* in_sizes, int n_in,
                              void* d_out, int out_size)
{
    const float* x0    = (const float*)d_in[0];
    const float* x1    = (const float*)d_in[1];
    const float* x2    = (const float*)d_in[2];
    const float* x3    = (const float*)d_in[3];
    const float* W0    = (const float*)d_in[4];
    const float* b0    = (const float*)d_in[5];
    const float* W1    = (const float*)d_in[6];
    const float* b1    = (const float*)d_in[7];
    const float* W2    = (const float*)d_in[8];
    const float* b2    = (const float*)d_in[9];
    const float* l1W   = (const float*)d_in[10];
    const float* l1b   = (const float*)d_in[11];
    const float* gamma = (const float*)d_in[12];
    const float* beta  = (const float*)d_in[13];
    const float* l2W   = (const float*)d_in[14];
    const float* l2b   = (const float*)d_in[15];
    float* out = (float*)d_out;

    void *p2 = nullptr, *p1 = nullptr, *p0 = nullptr;
    cudaGetSymbolAddress(&p2, g_h2m);
    cudaGetSymbolAddress(&p1, g_h1m);
    cudaGetSymbolAddress(&p0, g_h0);
    float* h2m = (float*)p2;
    float* h1m = (float*)p1;
    float* h0  = (float*)p0;

    cudaFuncSetAttribute(sage_mma<1, 1>,
                         cudaFuncAttributeMaxDynamicSharedMemorySize, SM_TOTAL);
    cudaFuncSetAttribute(sage_mma<0, 1>,
                         cudaFuncAttributeMaxDynamicSharedMemorySize, SM_TOTAL);
    cudaFuncSetAttribute(sage_mma<0, 0>,
                         cudaFuncAttributeMaxDynamicSharedMemorySize, SM_TOTAL);

    // K3 split into two launches (profiler alignment; negligible cost).
    // Pointers pre-offset so kernels use local row indexing; 'tile' (via
    // tile0) keeps the GLOBAL mean-row index for h2m.
    sage_mma<1, 1><<<148, THREADS, SM_TOTAL>>>(x3, x2, W2, b2, h2m, 1024, 0);
    sage_mma<1, 1><<<148, THREADS, SM_TOTAL>>>(
        x3 + (size_t)1024 * TILE * KAGG * F, x2 + (size_t)1024 * TILE * F,
        W2, b2, h2m, 1024, 1024);
    // K2: h2m ++ x1 -> relu GEMM -> 16-row means (h1m: 256 x 128)
    sage_mma<0, 1><<<128, THREADS, SM_TOTAL>>>(h2m, x1, W1, b1, h1m, 128, 0);
    // K1: h1m ++ x0 -> relu GEMM -> full h0 (256 x 128)
    sage_mma<0, 0><<<8, THREADS, SM_TOTAL>>>(h1m, x0, W0, b0, h0, 8, 0);
    // Head
    head_kernel<<<1, 512>>>(h0, l1W, l1b, gamma, beta, l2W, l2b, out);
}